// round 15
// baseline (speedup 1.0000x reference)
#include <cuda_runtime.h>
#include <math.h>

// MatchLoss: per src point (16384x3 f32), is the 2nd-nearest tgt within 1e-3?
// mv = (pd<1e-3)+1e-7, pd = ||src - tgt_2nd + 1e-6||; out = log(1+sum(exp(mv)))
//    = log(1 + (N-m)*e^eps + m*e^(1+eps)),  m = match count.
// Spatial hash, cell = 2.1e-3 >= 2*r_eff: radius ball fits in the 2x2x2 cell
// block picked by half-cell position -> 8 probe cells/src, 8 threads/src with
// ONE probe cell each. Chained buckets, gen-stamped heads (no clear).
// Coalesced phases: threads g<NPTS insert tgt[g] (dense warp loads); src
// coords loaded once per 8-lane group and shfl-broadcast.
#define NPTS      16384
#define HBITS     16
#define HSIZE     (1 << HBITS)
#define QSPLIT    8
#define THREADS   256
#define NB        (NPTS * QSPLIT / THREADS)   // 512 blocks, single wave

#define EPS_F     1e-7f
#define CELL_F    2.1e-3f
#define INV_CELL  (1.0f / CELL_F)
#define R2CUT     (1.05e-3f * 1.05e-3f)   // = (CELL/2)^2 coverage guarantee
#define RAD2      (1e-3f * 1e-3f)
#define BIG       3.402823466e+38f

__device__ unsigned long long g_head[HSIZE];   // (gen<<14)|idx ; stale gen = empty
__device__ int                g_next[NPTS];
__device__ long long          g_ckey[NPTS];
__device__ int                g_match = 0;
__device__ int                g_bar   = 0;
__device__ int                g_exit  = 0;
__device__ unsigned long long g_gen   = 1;     // bumped by last block each launch

__device__ __forceinline__ unsigned int cell_hash(int cx, int cy, int cz) {
    unsigned int h = (unsigned int)(cx * 73856093) ^
                     (unsigned int)(cy * 19349663) ^
                     (unsigned int)(cz * 83492791);
    return h & (HSIZE - 1);
}

__device__ __forceinline__ long long cell_key(int cx, int cy, int cz) {
    return (((long long)(cx + (1 << 20))) << 42) |
           (((long long)(cy + (1 << 20))) << 21) |
            ((long long)(cz + (1 << 20)));
}

__global__ __launch_bounds__(THREADS)
void ml_fused_kernel(const float* __restrict__ src, const float* __restrict__ tgt,
                     float* __restrict__ out) {
    __shared__ int swarp[THREADS / 32];
    const int tid  = threadIdx.x;
    const int lane = tid & 31;
    const int warp = tid >> 5;
    const int g    = blockIdx.x * THREADS + tid;   // 0..131071
    const int q    = g >> 3;                        // src index, 8 lanes each
    const int sub  = g & 7;                         // probe cell 0..7

    const unsigned long long gen = g_gen;           // consistent: set pre-launch

    // ---- Coalesced src load: 12 lanes/warp load 48 contiguous bytes, then
    //      broadcast to the 8-lane groups (4 q-values per warp). Issued first
    //      so the loads overlap the insert phase.
    const int base_q = (blockIdx.x * THREADS + warp * 32) >> 3;   // q of lane 0
    float v = 0.0f;
    if (lane < 12) v = src[3 * base_q + lane];
    const int gsel = 3 * (lane >> 3);               // 0,3,6,9
    const float px = __shfl_sync(0xFFFFFFFFu, v, gsel + 0);
    const float py = __shfl_sync(0xFFFFFFFFu, v, gsel + 1);
    const float pz = __shfl_sync(0xFFFFFFFFu, v, gsel + 2);

    // ---- Coalesced insert: threads g < NPTS insert tgt point g (dense) ----
    if (g < NPTS) {
        const float x = tgt[3 * g + 0], y = tgt[3 * g + 1], z = tgt[3 * g + 2];
        const int cx = (int)floorf(x * INV_CELL);
        const int cy = (int)floorf(y * INV_CELL);
        const int cz = (int)floorf(z * INV_CELL);
        g_ckey[g] = cell_key(cx, cy, cz);
        const unsigned long long old =
            atomicExch(&g_head[cell_hash(cx, cy, cz)],
                       (gen << 14) | (unsigned long long)g);
        g_next[g] = ((old >> 14) == gen) ? (int)(old & 16383ULL) : -1;
        __threadfence();           // release this writer's inserts
    }
    __syncthreads();

    // ---- Barrier ARRIVE (release); spin deferred until after setup ----
    if (tid == 0) atomicAdd(&g_bar, 1);

    // ---- Probe setup overlaps other blocks' inserts + barrier ----
    const float fx = px * INV_CELL, fy = py * INV_CELL, fz = pz * INV_CELL;
    const int cx = (int)floorf(fx);
    const int cy = (int)floorf(fy);
    const int cz = (int)floorf(fz);
    // base corner of the 2x2x2 block containing the radius ball
    const int bx = cx + ((fx - (float)cx >= 0.5f) ? 0 : -1);
    const int by = cy + ((fy - (float)cy >= 0.5f) ? 0 : -1);
    const int bz = cz + ((fz - (float)cz >= 0.5f) ? 0 : -1);

    // This lane's single probe cell: bits of sub -> (x,y,z) corner offset
    const int ccx = bx + (sub >> 2);
    const int ccy = by + ((sub >> 1) & 1);
    const int ccz = bz + (sub & 1);
    const long long    pkey  = cell_key(ccx, ccy, ccz);
    const unsigned int phash = cell_hash(ccx, ccy, ccz);

    // ---- Barrier WAIT (acquire) ----
    if (tid == 0) {
        while (*(volatile int*)&g_bar < NB) { __nanosleep(64); }
        __threadfence();
    }
    __syncthreads();

    // ---- Query: one head load; chains almost never occupied ----
    const unsigned long long hw = g_head[phash];
    int e = ((hw >> 14) == gen) ? (int)(hw & 16383ULL) : -1;

    float d1 = BIG, d2 = BIG;
    while (e >= 0) {                 // almost always 0 iterations
        const long long k  = g_ckey[e];      // independent loads: one round
        const float    tx  = tgt[3 * e + 0];
        const float    ty  = tgt[3 * e + 1];
        const float    tz  = tgt[3 * e + 2];
        const int      nx  = g_next[e];
        if (k == pkey) {
            const float ex = px - tx, ey = py - ty, ez = pz - tz;
            const float dd = fmaf(ex, ex, fmaf(ey, ey, ez * ez));
            d2 = fminf(d2, fmaxf(d1, dd));
            d1 = fminf(d1, dd);
        }
        e = nx;
    }

    // Merge top-2 values across the 8 lanes of this src point
    #pragma unroll
    for (int o = 1; o <= 4; o <<= 1) {
        const float o1 = __shfl_xor_sync(0xFFFFFFFFu, d1, o);
        const float o2 = __shfl_xor_sync(0xFFFFFFFFu, d2, o);
        d2 = fminf(fmaxf(d1, o1), fminf(d2, o2));
        d1 = fminf(d1, o1);
    }

    int m = 0;
    if (sub == 0 && d2 <= R2CUT) {
        // Rare exact path: rescan the 8 cells tracking coords, apply the
        // reference pd test (componentwise +1e-6 before the norm).
        float e1 = BIG, e2 = BIG;
        float q1x = 0, q1y = 0, q1z = 0, q2x = 0, q2y = 0, q2z = 0;
        for (int p = 0; p < 8; ++p) {
            const int rx = bx + (p >> 2);
            const int ry = by + ((p >> 1) & 1);
            const int rz = bz + (p & 1);
            const long long pk = cell_key(rx, ry, rz);
            const unsigned long long hw2 = g_head[cell_hash(rx, ry, rz)];
            int ee = ((hw2 >> 14) == gen) ? (int)(hw2 & 16383ULL) : -1;
            while (ee >= 0) {
                if (g_ckey[ee] == pk) {
                    const float tx = tgt[3 * ee + 0], ty = tgt[3 * ee + 1], tz = tgt[3 * ee + 2];
                    const float ex = px - tx, ey = py - ty, ez = pz - tz;
                    const float dd = fmaf(ex, ex, fmaf(ey, ey, ez * ez));
                    if (dd < e2) {
                        if (dd < e1) {
                            e2 = e1; q2x = q1x; q2y = q1y; q2z = q1z;
                            e1 = dd; q1x = tx;  q1y = ty;  q1z = tz;
                        } else {
                            e2 = dd; q2x = tx; q2y = ty; q2z = tz;
                        }
                    }
                }
                ee = g_next[ee];
            }
        }
        if (e2 <= R2CUT) {
            const float ex = px - q2x + 1e-6f;
            const float ey = py - q2y + 1e-6f;
            const float ez = pz - q2z + 1e-6f;
            if (fmaf(ex, ex, fmaf(ey, ey, ez * ez)) < RAD2) m = 1;
        }
    }

    // Deterministic integer reduction; one atomic per block
    #pragma unroll
    for (int o = 16; o > 0; o >>= 1)
        m += __shfl_down_sync(0xFFFFFFFFu, m, o);
    if (lane == 0) swarp[warp] = m;
    __syncthreads();

    if (tid == 0) {
        int bs = 0;
        #pragma unroll
        for (int w = 0; w < THREADS / 32; ++w) bs += swarp[w];
        if (bs) atomicAdd(&g_match, bs);
        __threadfence();
        // Last block to exit finalizes and restores state for graph replay.
        const int e2 = atomicAdd(&g_exit, 1);
        if (e2 == NB - 1) {
            const int mm = *(volatile int*)&g_match;
            const float S = (float)(NPTS - mm) * expf(EPS_F)
                          + (float)mm * expf(1.0f + EPS_F);
            out[0] = logf(1.0f + S);   // softplus(logsumexp(mv))
            g_match = 0;
            g_bar   = 0;
            g_exit  = 0;
            g_gen   = gen + 1;         // invalidates all buckets for next launch
            __threadfence();
        }
    }
}

extern "C" void kernel_launch(void* const* d_in, const int* in_sizes, int n_in,
                              void* d_out, int out_size) {
    const float* src = (const float*)d_in[0];  // src_coords [16384, 3]
    const float* tgt = (const float*)d_in[1];  // tgt_coords [16384, 3]
    float* out = (float*)d_out;
    ml_fused_kernel<<<NB, THREADS>>>(src, tgt, out);
}

// round 16
// speedup vs baseline: 1.0698x; 1.0698x over previous
#include <cuda_runtime.h>
#include <math.h>

// MatchLoss: per src point (16384x3 f32), is the 2nd-nearest tgt within 1e-3?
// mv = (pd<1e-3)+1e-7, pd = ||src - tgt_2nd + 1e-6||; out = log(1+sum(exp(mv)))
//    = log(1 + (N-m)*e^eps + m*e^(1+eps)),  m = match count.
// Spatial hash, cell = 2.1e-3 >= 2*r_eff: radius ball fits in the 2x2x2 cell
// block picked by half-cell position -> 8 probe cells/src, 8 threads/src with
// ONE probe cell each. Chained buckets, gen-stamped heads (no clear, no ckey
// array: chain filter recomputes the cell key from tgt coords). Gate is
// count(d2 < R2CUT) >= 2; rare exact fallback applies the reference pd test.
#define NPTS      16384
#define HBITS     16
#define HSIZE     (1 << HBITS)
#define QSPLIT    8
#define THREADS   256
#define NB        (NPTS * QSPLIT / THREADS)   // 512 blocks, single wave

#define EPS_F     1e-7f
#define CELL_F    2.1e-3f
#define INV_CELL  (1.0f / CELL_F)
#define R2CUT     (1.05e-3f * 1.05e-3f)   // = (CELL/2)^2 coverage guarantee
#define RAD2      (1e-3f * 1e-3f)
#define BIG       3.402823466e+38f

__device__ unsigned long long g_head[HSIZE];   // (gen<<14)|idx ; stale gen = empty
__device__ int                g_next[NPTS];
__device__ int                g_match = 0;
__device__ int                g_bar   = 0;
__device__ int                g_exit  = 0;
__device__ unsigned long long g_gen   = 1;     // bumped by last block each launch

__device__ __forceinline__ unsigned int cell_hash(int cx, int cy, int cz) {
    unsigned int h = (unsigned int)(cx * 73856093) ^
                     (unsigned int)(cy * 19349663) ^
                     (unsigned int)(cz * 83492791);
    return h & (HSIZE - 1);
}

__device__ __forceinline__ long long cell_key(int cx, int cy, int cz) {
    return (((long long)(cx + (1 << 20))) << 42) |
           (((long long)(cy + (1 << 20))) << 21) |
            ((long long)(cz + (1 << 20)));
}

__global__ __launch_bounds__(THREADS)
void ml_fused_kernel(const float* __restrict__ src, const float* __restrict__ tgt,
                     float* __restrict__ out) {
    __shared__ int swarp[THREADS / 32];
    const int tid  = threadIdx.x;
    const int lane = tid & 31;
    const int warp = tid >> 5;
    const int g    = blockIdx.x * THREADS + tid;   // 0..131071
    const int q    = g >> 3;                        // src index, 8 lanes each
    const int sub  = g & 7;                         // probe cell 0..7

    const unsigned long long gen = g_gen;           // consistent: set pre-launch

    // ---- Issue src loads immediately (overlap the insert round) ----
    const float px = src[3 * q + 0], py = src[3 * q + 1], pz = src[3 * q + 2];

    // ---- Insert tgt points (one lane in eight); 2 memory ops per insert ----
    if (sub == 0) {
        const float x = tgt[3 * q + 0], y = tgt[3 * q + 1], z = tgt[3 * q + 2];
        const int cx = (int)floorf(x * INV_CELL);
        const int cy = (int)floorf(y * INV_CELL);
        const int cz = (int)floorf(z * INV_CELL);
        const unsigned long long old =
            atomicExch(&g_head[cell_hash(cx, cy, cz)],
                       (gen << 14) | (unsigned long long)q);
        g_next[q] = ((old >> 14) == gen) ? (int)(old & 16383ULL) : -1;
        __threadfence();           // release this writer's inserts
    }
    __syncthreads();

    // ---- Barrier ARRIVE (release); spin deferred until after setup ----
    if (tid == 0) atomicAdd(&g_bar, 1);

    // ---- Probe setup overlaps other blocks' inserts + barrier ----
    const float fx = px * INV_CELL, fy = py * INV_CELL, fz = pz * INV_CELL;
    const int cx = (int)floorf(fx);
    const int cy = (int)floorf(fy);
    const int cz = (int)floorf(fz);
    // base corner of the 2x2x2 block containing the radius ball
    const int bx = cx + ((fx - (float)cx >= 0.5f) ? 0 : -1);
    const int by = cy + ((fy - (float)cy >= 0.5f) ? 0 : -1);
    const int bz = cz + ((fz - (float)cz >= 0.5f) ? 0 : -1);

    // This lane's single probe cell: bits of sub -> (x,y,z) corner offset
    const int ccx = bx + (sub >> 2);
    const int ccy = by + ((sub >> 1) & 1);
    const int ccz = bz + (sub & 1);
    const long long    pkey  = cell_key(ccx, ccy, ccz);
    const unsigned int phash = cell_hash(ccx, ccy, ccz);

    // ---- Barrier WAIT (acquire), plain spin ----
    if (tid == 0) {
        while (*(volatile int*)&g_bar < NB) { }
        __threadfence();
    }
    __syncthreads();

    // ---- Query: one head load; chain filter recomputes key from coords ----
    const unsigned long long hw = g_head[phash];
    int e = ((hw >> 14) == gen) ? (int)(hw & 16383ULL) : -1;

    int cnt = 0;
    while (e >= 0) {                 // usually 0 iterations (25% heads occupied)
        const float tx = tgt[3 * e + 0];
        const float ty = tgt[3 * e + 1];
        const float tz = tgt[3 * e + 2];
        const int   nx = g_next[e];  // independent of tgt loads: one round
        const long long tk = cell_key((int)floorf(tx * INV_CELL),
                                      (int)floorf(ty * INV_CELL),
                                      (int)floorf(tz * INV_CELL));
        if (tk == pkey) {
            const float ex = px - tx, ey = py - ty, ez = pz - tz;
            const float dd = fmaf(ex, ex, fmaf(ey, ey, ez * ez));
            cnt += (dd < R2CUT) ? 1 : 0;
        }
        e = nx;
    }

    // Sum candidate counts across the 8 lanes of this src point
    #pragma unroll
    for (int o = 1; o <= 4; o <<= 1)
        cnt += __shfl_xor_sync(0xFFFFFFFFu, cnt, o);

    int m = 0;
    if (sub == 0 && cnt >= 2) {
        // Rare exact path: rescan the 8 cells tracking coords, exact top-2,
        // then the reference pd test (componentwise +1e-6 before the norm).
        float e1 = BIG, e2 = BIG;
        float q1x = 0, q1y = 0, q1z = 0, q2x = 0, q2y = 0, q2z = 0;
        for (int p = 0; p < 8; ++p) {
            const int rx = bx + (p >> 2);
            const int ry = by + ((p >> 1) & 1);
            const int rz = bz + (p & 1);
            const long long pk = cell_key(rx, ry, rz);
            const unsigned long long hw2 = g_head[cell_hash(rx, ry, rz)];
            int ee = ((hw2 >> 14) == gen) ? (int)(hw2 & 16383ULL) : -1;
            while (ee >= 0) {
                const float tx = tgt[3 * ee + 0], ty = tgt[3 * ee + 1], tz = tgt[3 * ee + 2];
                const long long tk = cell_key((int)floorf(tx * INV_CELL),
                                              (int)floorf(ty * INV_CELL),
                                              (int)floorf(tz * INV_CELL));
                if (tk == pk) {
                    const float ex = px - tx, ey = py - ty, ez = pz - tz;
                    const float dd = fmaf(ex, ex, fmaf(ey, ey, ez * ez));
                    if (dd < e2) {
                        if (dd < e1) {
                            e2 = e1; q2x = q1x; q2y = q1y; q2z = q1z;
                            e1 = dd; q1x = tx;  q1y = ty;  q1z = tz;
                        } else {
                            e2 = dd; q2x = tx; q2y = ty; q2z = tz;
                        }
                    }
                }
                ee = g_next[ee];
            }
        }
        if (e2 <= R2CUT) {
            const float ex = px - q2x + 1e-6f;
            const float ey = py - q2y + 1e-6f;
            const float ez = pz - q2z + 1e-6f;
            if (fmaf(ex, ex, fmaf(ey, ey, ez * ez)) < RAD2) m = 1;
        }
    }

    // Deterministic integer reduction; atomics only when matches exist
    #pragma unroll
    for (int o = 16; o > 0; o >>= 1)
        m += __shfl_down_sync(0xFFFFFFFFu, m, o);
    if (lane == 0) swarp[warp] = m;
    __syncthreads();

    if (tid == 0) {
        int bs = 0;
        #pragma unroll
        for (int w = 0; w < THREADS / 32; ++w) bs += swarp[w];
        if (bs) atomicAdd(&g_match, bs);
        __threadfence();
        // Last block to exit finalizes and restores state for graph replay.
        const int e2 = atomicAdd(&g_exit, 1);
        if (e2 == NB - 1) {
            const int mm = *(volatile int*)&g_match;
            const float S = (float)(NPTS - mm) * expf(EPS_F)
                          + (float)mm * expf(1.0f + EPS_F);
            out[0] = logf(1.0f + S);   // softplus(logsumexp(mv))
            g_match = 0;
            g_bar   = 0;
            g_exit  = 0;
            g_gen   = gen + 1;         // invalidates all buckets for next launch
            __threadfence();
        }
    }
}

extern "C" void kernel_launch(void* const* d_in, const int* in_sizes, int n_in,
                              void* d_out, int out_size) {
    const float* src = (const float*)d_in[0];  // src_coords [16384, 3]
    const float* tgt = (const float*)d_in[1];  // tgt_coords [16384, 3]
    float* out = (float*)d_out;
    ml_fused_kernel<<<NB, THREADS>>>(src, tgt, out);
}

// round 17
// speedup vs baseline: 1.2249x; 1.1450x over previous
#include <cuda_runtime.h>
#include <math.h>

// MatchLoss: per src point (16384x3 f32), is the 2nd-nearest tgt within 1e-3?
// mv = (pd<1e-3)+1e-7, pd = ||src - tgt_2nd + 1e-6||; out = log(1+sum(exp(mv)))
//    = log(1 + (N-m)*e^eps + m*e^(1+eps)),  m = match count.
// Spatial hash, cell = 2.1e-3 >= 2*r_eff: radius ball fits in the 2x2x2 cell
// block picked by half-cell position -> 8 probe cells/src, 8 threads/src with
// ONE probe cell each. Chained buckets, gen-stamped heads (no clear, no ckey
// array). Two kernels coupled by PDL: build inserts + triggers; query launches
// early, runs its preamble concurrently, then cudaGridDependencySynchronize().
#define NPTS      16384
#define HBITS     16
#define HSIZE     (1 << HBITS)
#define QSPLIT    8
#define THREADS   256
#define NB_BUILD  (NPTS / THREADS)             // 64 blocks
#define NB_QUERY  (NPTS * QSPLIT / THREADS)    // 512 blocks

#define EPS_F     1e-7f
#define CELL_F    2.1e-3f
#define INV_CELL  (1.0f / CELL_F)
#define R2CUT     (1.05e-3f * 1.05e-3f)   // = (CELL/2)^2 coverage guarantee
#define RAD2      (1e-3f * 1e-3f)
#define BIG       3.402823466e+38f

__device__ unsigned long long g_head[HSIZE];   // (gen<<14)|idx ; stale gen = empty
__device__ int                g_next[NPTS];
__device__ int                g_match = 0;
__device__ int                g_exit  = 0;
__device__ unsigned long long g_gen   = 1;     // bumped by last query block

__device__ __forceinline__ unsigned int cell_hash(int cx, int cy, int cz) {
    unsigned int h = (unsigned int)(cx * 73856093) ^
                     (unsigned int)(cy * 19349663) ^
                     (unsigned int)(cz * 83492791);
    return h & (HSIZE - 1);
}

__device__ __forceinline__ long long cell_key(int cx, int cy, int cz) {
    return (((long long)(cx + (1 << 20))) << 42) |
           (((long long)(cy + (1 << 20))) << 21) |
            ((long long)(cz + (1 << 20)));
}

// ---- Build: one coalesced insert per thread, then PDL trigger ----
__global__ __launch_bounds__(THREADS)
void ml_build_kernel(const float* __restrict__ tgt) {
    const int i = blockIdx.x * THREADS + threadIdx.x;   // 0..16383
    const unsigned long long gen = g_gen;
    const float x = tgt[3 * i + 0], y = tgt[3 * i + 1], z = tgt[3 * i + 2];
    const int cx = (int)floorf(x * INV_CELL);
    const int cy = (int)floorf(y * INV_CELL);
    const int cz = (int)floorf(z * INV_CELL);
    const unsigned long long old =
        atomicExch(&g_head[cell_hash(cx, cy, cz)],
                   (gen << 14) | (unsigned long long)i);
    g_next[i] = ((old >> 14) == gen) ? (int)(old & 16383ULL) : -1;
    __threadfence();
    cudaTriggerProgrammaticLaunchCompletion();   // let query CTAs launch now
}

// ---- Query: preamble overlaps build via PDL; hardware dependency sync ----
__global__ __launch_bounds__(THREADS)
void ml_query_kernel(const float* __restrict__ src, const float* __restrict__ tgt,
                     float* __restrict__ out) {
    __shared__ int swarp[THREADS / 32];
    const int tid  = threadIdx.x;
    const int lane = tid & 31;
    const int warp = tid >> 5;
    const int g    = blockIdx.x * THREADS + tid;   // 0..131071
    const int q    = g >> 3;                        // src index, 8 lanes each
    const int sub  = g & 7;                         // probe cell 0..7

    const unsigned long long gen = g_gen;           // stable during this graph node

    // ---- Preamble (runs concurrently with build): src load + probe setup ----
    const float px = src[3 * q + 0], py = src[3 * q + 1], pz = src[3 * q + 2];
    const float fx = px * INV_CELL, fy = py * INV_CELL, fz = pz * INV_CELL;
    const int cx = (int)floorf(fx);
    const int cy = (int)floorf(fy);
    const int cz = (int)floorf(fz);
    // base corner of the 2x2x2 block containing the radius ball
    const int bx = cx + ((fx - (float)cx >= 0.5f) ? 0 : -1);
    const int by = cy + ((fy - (float)cy >= 0.5f) ? 0 : -1);
    const int bz = cz + ((fz - (float)cz >= 0.5f) ? 0 : -1);

    // This lane's single probe cell: bits of sub -> (x,y,z) corner offset
    const int ccx = bx + (sub >> 2);
    const int ccy = by + ((sub >> 1) & 1);
    const int ccz = bz + (sub & 1);
    const long long    pkey  = cell_key(ccx, ccy, ccz);
    const unsigned int phash = cell_hash(ccx, ccy, ccz);

    // ---- Hardware wait: all build-grid writes visible after this ----
    cudaGridDependencySynchronize();

    // ---- Query: one head load; chain filter recomputes key from coords ----
    const unsigned long long hw = g_head[phash];
    int e = ((hw >> 14) == gen) ? (int)(hw & 16383ULL) : -1;

    int cnt = 0;
    while (e >= 0) {                 // usually 0 iterations (25% heads occupied)
        const float tx = tgt[3 * e + 0];
        const float ty = tgt[3 * e + 1];
        const float tz = tgt[3 * e + 2];
        const int   nx = g_next[e];  // independent of tgt loads: one round
        const long long tk = cell_key((int)floorf(tx * INV_CELL),
                                      (int)floorf(ty * INV_CELL),
                                      (int)floorf(tz * INV_CELL));
        if (tk == pkey) {
            const float ex = px - tx, ey = py - ty, ez = pz - tz;
            const float dd = fmaf(ex, ex, fmaf(ey, ey, ez * ez));
            cnt += (dd < R2CUT) ? 1 : 0;
        }
        e = nx;
    }

    // Sum candidate counts across the 8 lanes of this src point
    #pragma unroll
    for (int o = 1; o <= 4; o <<= 1)
        cnt += __shfl_xor_sync(0xFFFFFFFFu, cnt, o);

    int m = 0;
    if (sub == 0 && cnt >= 2) {
        // Rare exact path: rescan the 8 cells tracking coords, exact top-2,
        // then the reference pd test (componentwise +1e-6 before the norm).
        float e1 = BIG, e2 = BIG;
        float q1x = 0, q1y = 0, q1z = 0, q2x = 0, q2y = 0, q2z = 0;
        for (int p = 0; p < 8; ++p) {
            const int rx = bx + (p >> 2);
            const int ry = by + ((p >> 1) & 1);
            const int rz = bz + (p & 1);
            const long long pk = cell_key(rx, ry, rz);
            const unsigned long long hw2 = g_head[cell_hash(rx, ry, rz)];
            int ee = ((hw2 >> 14) == gen) ? (int)(hw2 & 16383ULL) : -1;
            while (ee >= 0) {
                const float tx = tgt[3 * ee + 0], ty = tgt[3 * ee + 1], tz = tgt[3 * ee + 2];
                const long long tk = cell_key((int)floorf(tx * INV_CELL),
                                              (int)floorf(ty * INV_CELL),
                                              (int)floorf(tz * INV_CELL));
                if (tk == pk) {
                    const float ex = px - tx, ey = py - ty, ez = pz - tz;
                    const float dd = fmaf(ex, ex, fmaf(ey, ey, ez * ez));
                    if (dd < e2) {
                        if (dd < e1) {
                            e2 = e1; q2x = q1x; q2y = q1y; q2z = q1z;
                            e1 = dd; q1x = tx;  q1y = ty;  q1z = tz;
                        } else {
                            e2 = dd; q2x = tx; q2y = ty; q2z = tz;
                        }
                    }
                }
                ee = g_next[ee];
            }
        }
        if (e2 <= R2CUT) {
            const float ex = px - q2x + 1e-6f;
            const float ey = py - q2y + 1e-6f;
            const float ez = pz - q2z + 1e-6f;
            if (fmaf(ex, ex, fmaf(ey, ey, ez * ez)) < RAD2) m = 1;
        }
    }

    // Deterministic integer reduction; atomics only when matches exist
    #pragma unroll
    for (int o = 16; o > 0; o >>= 1)
        m += __shfl_down_sync(0xFFFFFFFFu, m, o);
    if (lane == 0) swarp[warp] = m;
    __syncthreads();

    if (tid == 0) {
        int bs = 0;
        #pragma unroll
        for (int w = 0; w < THREADS / 32; ++w) bs += swarp[w];
        if (bs) atomicAdd(&g_match, bs);
        __threadfence();
        // Last block to exit finalizes and restores state for graph replay.
        const int e2 = atomicAdd(&g_exit, 1);
        if (e2 == NB_QUERY - 1) {
            const int mm = *(volatile int*)&g_match;
            const float S = (float)(NPTS - mm) * expf(EPS_F)
                          + (float)mm * expf(1.0f + EPS_F);
            out[0] = logf(1.0f + S);   // softplus(logsumexp(mv))
            g_match = 0;
            g_exit  = 0;
            g_gen   = gen + 1;         // invalidates all buckets for next replay
            __threadfence();
        }
    }
}

extern "C" void kernel_launch(void* const* d_in, const int* in_sizes, int n_in,
                              void* d_out, int out_size) {
    const float* src = (const float*)d_in[0];  // src_coords [16384, 3]
    const float* tgt = (const float*)d_in[1];  // tgt_coords [16384, 3]
    float* out = (float*)d_out;

    ml_build_kernel<<<NB_BUILD, THREADS>>>(tgt);

    // Query kernel with programmatic dependent launch: CTAs may launch before
    // build completes; cudaGridDependencySynchronize() provides the ordering.
    cudaLaunchConfig_t cfg = {};
    cfg.gridDim  = dim3(NB_QUERY, 1, 1);
    cfg.blockDim = dim3(THREADS, 1, 1);
    cfg.dynamicSmemBytes = 0;
    cfg.stream = 0;
    cudaLaunchAttribute attr[1];
    attr[0].id = cudaLaunchAttributeProgrammaticStreamSerialization;
    attr[0].val.programmaticStreamSerializationAllowed = 1;
    cfg.attrs = attr;
    cfg.numAttrs = 1;
    cudaLaunchKernelEx(&cfg, ml_query_kernel, src, tgt, out);
}